// round 5
// baseline (speedup 1.0000x reference)
#include <cuda_runtime.h>
#include <cuda_bf16.h>

// Scratch for pooled diff: [32, 128, 128] floats = 2 MB (static, no allocs).
__device__ float g_diff[32 * 128 * 128];

// Graph-replay-safe monotonic counters (each launch consumes a fixed amount;
// no resets ever needed).
__device__ unsigned            g_arrive = 0;  // +GRIDN per launch (barrier)
__device__ unsigned long long  g_work   = 0;  // +(NTILES+NWARPS) per launch
__device__ unsigned            g_epoch  = 0;  // +1 per launch (read at entry)

#define GRIDN  148
#define NWARPS (GRIDN * 32)          // 4736 warps total
#define NTILES (32 * 128 * 4)        // 16384 warp-tiles (b, py, 32-col group)
#define NSEG   (32 * 128 * 32)       // 131072 4-wide TV segments

__global__ __launch_bounds__(1024, 1) void fused_spa_kernel(
    const float* __restrict__ org, const float* __restrict__ enh,
    float* __restrict__ out)
{
    const int lane = threadIdx.x & 31;

    if (blockIdx.x == 0 && threadIdx.x == 0) out[0] = 0.f;

    // Per-launch work window (epoch is stable during phase 1: it is only
    // incremented after the grid barrier, i.e. after every block finished
    // phase 1 and has long since read it).
    const unsigned long long base =
        (unsigned long long)g_epoch * (unsigned long long)(NTILES + NWARPS);

    // ---- Phase 1: pooled channel-mean diff -> g_diff, work-stealing ----
    // Warp grabs tiles via global ticket; next ticket prefetched before
    // processing the current tile so the ATOMG latency is fully hidden.
    // Each warp ends on exactly ONE failing grab -> adds per launch are
    // exactly NTILES + NWARPS (deterministic across graph replays).
    int next_t = 0;
    if (lane == 0)
        next_t = (int)(atomicAdd(&g_work, 1ULL) - base);
    next_t = __shfl_sync(0xFFFFFFFFu, next_t, 0);

    while (next_t < NTILES) {
        const int t = next_t;
        if (lane == 0)
            next_t = (int)(atomicAdd(&g_work, 1ULL) - base);
        next_t = __shfl_sync(0xFFFFFFFFu, next_t, 0);

        const int b   = t >> 9;             // 512 warp-tiles per image
        const int rem = t & 511;
        const int py  = rem >> 2;
        const int pc  = ((rem & 3) << 5) + lane;

        float s = 0.f;
#pragma unroll
        for (int c = 0; c < 3; ++c) {
#pragma unroll
            for (int dy = 0; dy < 4; ++dy) {
                const size_t off = (((size_t)(b * 3 + c) * 512) + (size_t)(py * 4 + dy)) * 512
                                   + (size_t)(4 * pc);
                const float4 o = *reinterpret_cast<const float4*>(org + off);
                const float4 e = *reinterpret_cast<const float4*>(enh + off);
                s += (o.x - e.x) + (o.y - e.y) + (o.z - e.z) + (o.w - e.w);
            }
        }
        g_diff[(b << 14) + (py << 7) + pc] = s * (1.0f / 48.0f);
    }

    // ---- Grid barrier (all GRIDN blocks resident: grid == 148, occ 1) ----
    __syncthreads();
    if (threadIdx.x == 0) {
        __threadfence();             // publish g_diff (and out = 0)
        const unsigned ticket = atomicAdd(&g_arrive, 1u);
        const unsigned target = (ticket / GRIDN + 1u) * GRIDN;
        volatile unsigned* va = &g_arrive;
        while (*va < target) { }
        __threadfence();             // acquire all blocks' g_diff
    }
    __syncthreads();

    // Advance epoch for the next launch. Safe: every block has passed the
    // barrier, so all entry-time reads of g_epoch are complete.
    if (blockIdx.x == 0 && threadIdx.x == 0) g_epoch += 1u;

    // ---- Phase 2: 4-direction shift-diff^2 + full reduction ----
    const int tid = blockIdx.x * 1024 + threadIdx.x;   // 0 .. 151551
    float v = 0.f;
    if (tid < NSEG) {
        const int b  = tid >> 12;         // 4096 segments per image
        const int r  = tid & 4095;
        const int y  = r >> 5;            // row 0..127
        const int sx = (r & 31) << 2;     // segment start col

        const float* __restrict__ img = g_diff + ((size_t)b << 14);
        const int p = (y << 7) + sx;

        const float4 c = *reinterpret_cast<const float4*>(img + p);
        const float  l  = (sx > 0)   ? img[p - 1] : 0.f;
        const float  rr = (sx < 124) ? img[p + 4] : 0.f;

        float4 u, dn;
        if (y > 0)   u  = *reinterpret_cast<const float4*>(img + p - 128);
        else         u  = make_float4(0.f, 0.f, 0.f, 0.f);
        if (y < 127) dn = *reinterpret_cast<const float4*>(img + p + 128);
        else         dn = make_float4(0.f, 0.f, 0.f, 0.f);

        float a;
        a = c.x - l;    v += a * a;
        a = c.x - c.y;  v += a * a;
        a = c.x - u.x;  v += a * a;
        a = c.x - dn.x; v += a * a;

        a = c.y - c.x;  v += a * a;
        a = c.y - c.z;  v += a * a;
        a = c.y - u.y;  v += a * a;
        a = c.y - dn.y; v += a * a;

        a = c.z - c.y;  v += a * a;
        a = c.z - c.w;  v += a * a;
        a = c.z - u.z;  v += a * a;
        a = c.z - dn.z; v += a * a;

        a = c.w - c.z;  v += a * a;
        a = c.w - rr;   v += a * a;
        a = c.w - u.w;  v += a * a;
        a = c.w - dn.w; v += a * a;
    }

    // warp reduce
#pragma unroll
    for (int o = 16; o > 0; o >>= 1)
        v += __shfl_xor_sync(0xFFFFFFFFu, v, o);

    __shared__ float ws[32];
    if (lane == 0) ws[threadIdx.x >> 5] = v;
    __syncthreads();

    if (threadIdx.x < 32) {
        float vv = ws[threadIdx.x];
#pragma unroll
        for (int o = 16; o > 0; o >>= 1)
            vv += __shfl_xor_sync(0xFFFFFFFFu, vv, o);
        if (threadIdx.x == 0)
            atomicAdd(out, vv * (1.0f / (32.0f * 128.0f * 128.0f)));
    }
}

extern "C" void kernel_launch(void* const* d_in, const int* in_sizes, int n_in,
                              void* d_out, int out_size)
{
    const float* org = (const float*)d_in[0];
    const float* enh = (const float*)d_in[1];
    float* out = (float*)d_out;

    fused_spa_kernel<<<GRIDN, 1024>>>(org, enh, out);
}

// round 8
// speedup vs baseline: 1.2899x; 1.2899x over previous
#include <cuda_runtime.h>
#include <cuda_bf16.h>

// Scratch for pooled diff: [32, 128, 128] floats = 2 MB (static, no allocs).
__device__ float g_diff[32 * 128 * 128];

// K1: pooled diff. grid = (128 pooled rows, 32 batch), block = 128 threads
// (one thread per pooled column). Each thread reads 3 channels x 4 rows x
// float4 (its 4x4 block, all channels) from BOTH tensors -> 24 x 16B loads,
// fully coalesced across the warp. Also zeroes the scalar output (stream-
// ordered before K2's atomics). Signals PDL so K2 can spin up early.
__global__ __launch_bounds__(128) void pool_diff_kernel(
    const float* __restrict__ org, const float* __restrict__ enh,
    float* __restrict__ out)
{
    // Allow the dependent kernel (K2) to begin launching; it still waits on
    // griddepcontrol.wait before touching our output.
    asm volatile("griddepcontrol.launch_dependents;" ::: "memory");

    const int t  = threadIdx.x;   // pooled col 0..127
    const int py = blockIdx.x;    // pooled row 0..127
    const int b  = blockIdx.y;    // batch 0..31

    if (py == 0 && b == 0 && t == 0) out[0] = 0.f;

    float s = 0.f;
#pragma unroll
    for (int c = 0; c < 3; ++c) {
#pragma unroll
        for (int dy = 0; dy < 4; ++dy) {
            const size_t off = (((size_t)(b * 3 + c) * 512) + (size_t)(py * 4 + dy)) * 512
                               + (size_t)(4 * t);
            const float4 o = *reinterpret_cast<const float4*>(org + off);
            const float4 e = *reinterpret_cast<const float4*>(enh + off);
            s += (o.x - e.x) + (o.y - e.y) + (o.z - e.z) + (o.w - e.w);
        }
    }
    // mean over 3 channels and 16 pixels = /48
    g_diff[((b << 7) + py) * 128 + t] = s * (1.0f / 48.0f);
}

// K2: 4-direction shift-diff^2 + full reduction, vectorized (1 thread = one
// 4-wide row segment). 512 blocks x 256 threads = 131072 threads = NSEG.
// Launched with programmatic stream serialization: prologue overlaps K1.
__global__ __launch_bounds__(256) void tv_reduce_kernel(float* __restrict__ out)
{
    const int idx = blockIdx.x * 256 + threadIdx.x;   // 0 .. 131071
    const int b   = idx >> 12;        // 4096 segments per image
    const int r   = idx & 4095;
    const int y   = r >> 5;           // row 0..127
    const int sx  = (r & 31) << 2;    // segment start col: 0,4,...,124

    const float* __restrict__ img = g_diff + ((size_t)b << 14);
    const int p = (y << 7) + sx;

    // Wait for K1's memory to be visible before reading g_diff / out.
    asm volatile("griddepcontrol.wait;" ::: "memory");

    const float4 c  = *reinterpret_cast<const float4*>(img + p);
    const float  l  = (sx > 0)   ? img[p - 1] : 0.f;
    const float  rr = (sx < 124) ? img[p + 4] : 0.f;

    float4 u, dn;
    if (y > 0)   u  = *reinterpret_cast<const float4*>(img + p - 128);
    else         u  = make_float4(0.f, 0.f, 0.f, 0.f);
    if (y < 127) dn = *reinterpret_cast<const float4*>(img + p + 128);
    else         dn = make_float4(0.f, 0.f, 0.f, 0.f);

    float v;
    {
        float a;
        a = c.x - l;    v  = a * a;
        a = c.x - c.y;  v += a * a;
        a = c.x - u.x;  v += a * a;
        a = c.x - dn.x; v += a * a;

        a = c.y - c.x;  v += a * a;
        a = c.y - c.z;  v += a * a;
        a = c.y - u.y;  v += a * a;
        a = c.y - dn.y; v += a * a;

        a = c.z - c.y;  v += a * a;
        a = c.z - c.w;  v += a * a;
        a = c.z - u.z;  v += a * a;
        a = c.z - dn.z; v += a * a;

        a = c.w - c.z;  v += a * a;
        a = c.w - rr;   v += a * a;
        a = c.w - u.w;  v += a * a;
        a = c.w - dn.w; v += a * a;
    }

    // warp reduce
#pragma unroll
    for (int o = 16; o > 0; o >>= 1)
        v += __shfl_xor_sync(0xFFFFFFFFu, v, o);

    __shared__ float ws[8];
    if ((threadIdx.x & 31) == 0) ws[threadIdx.x >> 5] = v;
    __syncthreads();

    if (threadIdx.x < 32) {
        float vv = (threadIdx.x < 8) ? ws[threadIdx.x] : 0.f;
#pragma unroll
        for (int o = 4; o > 0; o >>= 1)
            vv += __shfl_xor_sync(0xFFFFFFFFu, vv, o);
        if (threadIdx.x == 0)
            atomicAdd(out, vv * (1.0f / (32.0f * 128.0f * 128.0f)));
    }
}

extern "C" void kernel_launch(void* const* d_in, const int* in_sizes, int n_in,
                              void* d_out, int out_size)
{
    const float* org = (const float*)d_in[0];
    const float* enh = (const float*)d_in[1];
    float* out = (float*)d_out;

    dim3 g1(128, 32);
    pool_diff_kernel<<<g1, 128>>>(org, enh, out);

    // K2 with programmatic dependent launch: spins up during K1, waits for
    // K1's completion inside the kernel (griddepcontrol.wait).
    cudaLaunchConfig_t cfg = {};
    cfg.gridDim  = dim3(512, 1, 1);
    cfg.blockDim = dim3(256, 1, 1);
    cfg.dynamicSmemBytes = 0;
    cfg.stream = 0;

    cudaLaunchAttribute attr[1];
    attr[0].id = cudaLaunchAttributeProgrammaticStreamSerialization;
    attr[0].val.programmaticStreamSerializationAllowed = 1;
    cfg.attrs = attr;
    cfg.numAttrs = 1;

    cudaLaunchKernelEx(&cfg, tv_reduce_kernel, out);
}